// round 3
// baseline (speedup 1.0000x reference)
#include <cuda_runtime.h>
#include <math.h>

#define H      128
#define H3     384
#define BATCH  64
#define TT     2048
#define TILE   128   // time steps staged per smem chunk

typedef unsigned long long ull_t;

// feat[b*256 + dir*128 + i] = mean over t of hidden state
__device__ float g_feat[BATCH * 2 * H];

__device__ __forceinline__ ull_t pack2(float lo, float hi) {
    return (ull_t)__float_as_uint(lo) | ((ull_t)__float_as_uint(hi) << 32);
}
__device__ __forceinline__ float lo2(ull_t v) { return __uint_as_float((unsigned)v); }
__device__ __forceinline__ float hi2(ull_t v) { return __uint_as_float((unsigned)(v >> 32)); }

__device__ __forceinline__ ull_t ffma2(ull_t a, ull_t b, ull_t c) {
    ull_t d;
    asm("fma.rn.f32x2 %0, %1, %2, %3;" : "=l"(d) : "l"(a), "l"(b), "l"(c));
    return d;
}
__device__ __forceinline__ ull_t fadd2(ull_t a, ull_t b) {
    ull_t d;
    asm("add.rn.f32x2 %0, %1, %2;" : "=l"(d) : "l"(a), "l"(b));
    return d;
}
__device__ __forceinline__ float ex2f(float x) {
    float r; asm("ex2.approx.ftz.f32 %0, %1;" : "=f"(r) : "f"(x)); return r;
}
__device__ __forceinline__ float rcpf(float x) {
    float r; asm("rcp.approx.ftz.f32 %0, %1;" : "=f"(r) : "f"(x)); return r;
}

#define L2E 1.4426950408889634f

// sigmoid(x) = 1 / (1 + 2^(-x*log2e))
__device__ __forceinline__ float fsig(float x) {
    return rcpf(1.0f + ex2f(-L2E * x));
}
// tanh(x) = 2/(1+2^(-2*log2e*x)) - 1  (callers fold the affine part)
__device__ __forceinline__ float ftanh(float x) {
    return 2.0f * rcpf(1.0f + ex2f(-2.0f * L2E * x)) - 1.0f;
}

// One persistent block per (batch, direction). 384 threads; thread j owns
// column j of the 3H pre-activations with Wh[:,j] packed f32x2 in registers.
// j <  128: r-gate column j        -> writes r_s
// j <  256: z-gate column j-128    -> writes omz2_s = 2(1-z), zhm_s = z*h-(1-z)
// j >= 256: n-gate column j-256    -> performs the h update.
__global__ void __launch_bounds__(H3, 1) gru_persist_kernel(
    const float* __restrict__ y, const float* __restrict__ u,
    const float* __restrict__ Wi_f, const float* __restrict__ bi_f,
    const float* __restrict__ Wh_f, const float* __restrict__ bhn_f,
    const float* __restrict__ Wi_b, const float* __restrict__ bi_b,
    const float* __restrict__ Wh_b, const float* __restrict__ bhn_b)
{
    const int blk = blockIdx.x;        // 0..127
    const int b   = blk & (BATCH - 1); // batch index
    const int dir = blk >> 6;          // 0 = fwd, 1 = bwd
    const int j   = threadIdx.x;       // 0..383

    const float* Wi  = dir ? Wi_b  : Wi_f;
    const float* bi  = dir ? bi_b  : bi_f;
    const float* Wh  = dir ? Wh_b  : Wh_f;
    const float* bhn = dir ? bhn_b : bhn_f;

    // ---- register-resident weights, packed pairs along k ----
    ull_t w2[H / 2];
#pragma unroll
    for (int kk = 0; kk < H / 2; ++kk)
        w2[kk] = pack2(Wh[(2 * kk) * H3 + j], Wh[(2 * kk + 1) * H3 + j]);

    ull_t wi2[4];
#pragma unroll
    for (int d = 0; d < 4; ++d)
        wi2[d] = pack2(Wi[(2 * d) * H3 + j], Wi[(2 * d + 1) * H3 + j]);

    const ull_t bij2  = pack2(bi[j], 0.0f);
    const float bhn_i = (j >= 2 * H) ? bhn[j - 2 * H] : 0.0f;

    // ---- shared state ----
    __shared__ __align__(16) float h_s[H];   // hidden state
    __shared__ float r_s[H], omz2_s[H], zhm_s[H];
    __shared__ __align__(16) float4 yu_s[TILE * 2];   // per step: y(4)+u(4)

    if (j < H) h_s[j] = 0.0f;
    __syncthreads();

    float hsum = 0.0f;                       // running sum (n-threads only)

    const int nchunk = TT / TILE;
    for (int c = 0; c < nchunk; ++c) {
        const int t0 = dir ? (TT - (c + 1) * TILE) : (c * TILE);

        if (j < TILE) {                      // stage chunk inputs
            const int t = t0 + j;
            yu_s[2 * j]     = *(const float4*)(y + ((size_t)b * TT + t) * 4);
            yu_s[2 * j + 1] = *(const float4*)(u + ((size_t)b * TT + t) * 4);
        }
        __syncthreads();

        for (int s = 0; s < TILE; ++s) {
            const int tt = dir ? (TILE - 1 - s) : s;

            // ---- phase 1: pre-activations (all threads) ----
            const ulonglong2 yv = ((const ulonglong2*)yu_s)[2 * tt];
            const ulonglong2 uv = ((const ulonglong2*)yu_s)[2 * tt + 1];
            ull_t xp = ffma2(yv.x, wi2[0], bij2);
            xp = ffma2(yv.y, wi2[1], xp);
            xp = ffma2(uv.x, wi2[2], xp);
            xp = ffma2(uv.y, wi2[3], xp);
            const float xw = lo2(xp) + hi2(xp);

            // packed dot: h[0:128] . w2
            const ulonglong2* h2 = (const ulonglong2*)h_s;
            ull_t a0 = 0ull, a1 = 0ull;
#pragma unroll
            for (int m = 0; m < H / 4; ++m) {
                const ulonglong2 hv = h2[m];          // broadcast
                a0 = ffma2(hv.x, w2[2 * m],     a0);
                a1 = ffma2(hv.y, w2[2 * m + 1], a1);
            }
            const ull_t asum = fadd2(a0, a1);
            const float dot = lo2(asum) + hi2(asum);

            float nb = 0.0f;   // n-thread keeps dot+bhn
            if (j < H) {
                r_s[j] = fsig(xw + dot);
            } else if (j < 2 * H) {
                const int i = j - H;
                const float z = fsig(xw + dot);
                const float hold = h_s[i];
                omz2_s[i] = 2.0f - 2.0f * z;
                zhm_s[i]  = fmaf(z, hold + 1.0f, -1.0f);   // z*h - (1-z)
            } else {
                nb = dot + bhn_i;
            }
            __syncthreads();

            // ---- phase 2: n-gate threads do the state update ----
            if (j >= 2 * H) {
                const int i = j - 2 * H;
                const float om = omz2_s[i];            // off critical path
                const float zm = zhm_s[i];
                const float r  = r_s[i];
                const float arg = fmaf(r, nb, xw);
                const float q   = ex2f(-2.0f * L2E * arg);
                const float rc  = rcpf(1.0f + q);
                const float hn  = fmaf(rc, om, zm);    // (1-z)*tanh + z*h
                hsum += hn;
                h_s[i] = hn;
            }
            __syncthreads();
        }
    }

    if (j >= 2 * H)
        g_feat[b * (2 * H) + dir * H + (j - 2 * H)] = hsum * (1.0f / (float)TT);
}

// MLP heads: 256 -> 128 -> 64 -> 20, tanh, tanh, linear.
// One block per (batch, head), 256 threads; layer-0 dot split across 2 halves.
__global__ void __launch_bounds__(256) mlp_kernel(
    const float* __restrict__ mW0, const float* __restrict__ mb0,
    const float* __restrict__ mW1, const float* __restrict__ mb1,
    const float* __restrict__ mW2, const float* __restrict__ mb2,
    const float* __restrict__ sW0, const float* __restrict__ sb0,
    const float* __restrict__ sW1, const float* __restrict__ sb1,
    const float* __restrict__ sW2, const float* __restrict__ sb2,
    float* __restrict__ out)
{
    const int b    = blockIdx.x & (BATCH - 1);
    const int head = blockIdx.x >> 6;
    const int tid  = threadIdx.x;

    const float* W0 = head ? sW0 : mW0;
    const float* b0 = head ? sb0 : mb0;
    const float* W1 = head ? sW1 : mW1;
    const float* b1 = head ? sb1 : mb1;
    const float* W2 = head ? sW2 : mW2;
    const float* b2 = head ? sb2 : mb2;

    __shared__ float feat_s[256];
    __shared__ float part[2][128];
    __shared__ float h1_s[128];
    __shared__ float h2_s[64];

    feat_s[tid] = g_feat[b * 256 + tid];
    __syncthreads();

    // layer 0: 256 -> 128, split reduction over two halves
    {
        const int j = tid & 127, half = tid >> 7;
        float acc = half ? 0.0f : b0[j];
        const int i0 = half * 128;
#pragma unroll 16
        for (int i = 0; i < 128; ++i)
            acc = fmaf(feat_s[i0 + i], __ldg(W0 + (size_t)(i0 + i) * 128 + j), acc);
        part[half][j] = acc;
    }
    __syncthreads();
    if (tid < 128) h1_s[tid] = ftanh(part[0][tid] + part[1][tid]);
    __syncthreads();

    // layer 1: 128 -> 64, split reduction over two halves (threads 0..127)
    if (tid < 128) {
        const int j = tid & 63, half = tid >> 6;
        float acc = half ? 0.0f : b1[j];
        const int i0 = half * 64;
#pragma unroll 16
        for (int i = 0; i < 64; ++i)
            acc = fmaf(h1_s[i0 + i], __ldg(W1 + (size_t)(i0 + i) * 64 + j), acc);
        part[half][j] = acc;
    }
    __syncthreads();
    if (tid < 64) h2_s[tid] = ftanh(part[0][tid] + part[1][tid]);
    __syncthreads();

    // layer 2: 64 -> 20
    if (tid < 20) {
        float acc = b2[tid];
#pragma unroll
        for (int i = 0; i < 64; ++i)
            acc = fmaf(h2_s[i], __ldg(W2 + (size_t)i * 20 + tid), acc);
        out[head * (BATCH * 20) + b * 20 + tid] = acc;
    }
}

extern "C" void kernel_launch(void* const* d_in, const int* in_sizes, int n_in,
                              void* d_out, int out_size)
{
    const float* y     = (const float*)d_in[0];
    const float* u     = (const float*)d_in[1];
    const float* Wi_f  = (const float*)d_in[2];
    const float* bi_f  = (const float*)d_in[3];
    const float* Wh_f  = (const float*)d_in[4];
    const float* bhn_f = (const float*)d_in[5];
    const float* Wi_b  = (const float*)d_in[6];
    const float* bi_b  = (const float*)d_in[7];
    const float* Wh_b  = (const float*)d_in[8];
    const float* bhn_b = (const float*)d_in[9];
    const float* mW0   = (const float*)d_in[10];
    const float* mb0   = (const float*)d_in[11];
    const float* mW1   = (const float*)d_in[12];
    const float* mb1   = (const float*)d_in[13];
    const float* mW2   = (const float*)d_in[14];
    const float* mb2   = (const float*)d_in[15];
    const float* sW0   = (const float*)d_in[16];
    const float* sb0   = (const float*)d_in[17];
    const float* sW1   = (const float*)d_in[18];
    const float* sb1   = (const float*)d_in[19];
    const float* sW2   = (const float*)d_in[20];
    const float* sb2   = (const float*)d_in[21];

    gru_persist_kernel<<<BATCH * 2, H3>>>(y, u, Wi_f, bi_f, Wh_f, bhn_f,
                                          Wi_b, bi_b, Wh_b, bhn_b);
    mlp_kernel<<<BATCH * 2, 256>>>(mW0, mb0, mW1, mb1, mW2, mb2,
                                   sW0, sb0, sW1, sb1, sW2, sb2,
                                   (float*)d_out);
}

// round 4
// speedup vs baseline: 1.0306x; 1.0306x over previous
#include <cuda_runtime.h>
#include <math.h>

#define H      128
#define H3     384
#define BATCH  64
#define TT     2048
#define TILE   128   // time steps staged per smem chunk

typedef unsigned long long ull_t;

// feat[b*256 + dir*128 + i] = mean over t of hidden state
__device__ float g_feat[BATCH * 2 * H];

__device__ __forceinline__ ull_t pack2(float lo, float hi) {
    return (ull_t)__float_as_uint(lo) | ((ull_t)__float_as_uint(hi) << 32);
}
__device__ __forceinline__ float lo2(ull_t v) { return __uint_as_float((unsigned)v); }
__device__ __forceinline__ float hi2(ull_t v) { return __uint_as_float((unsigned)(v >> 32)); }

__device__ __forceinline__ ull_t ffma2(ull_t a, ull_t b, ull_t c) {
    ull_t d;
    asm("fma.rn.f32x2 %0, %1, %2, %3;" : "=l"(d) : "l"(a), "l"(b), "l"(c));
    return d;
}
__device__ __forceinline__ ull_t fadd2(ull_t a, ull_t b) {
    ull_t d;
    asm("add.rn.f32x2 %0, %1, %2;" : "=l"(d) : "l"(a), "l"(b));
    return d;
}
__device__ __forceinline__ float ex2f(float x) {
    float r; asm("ex2.approx.ftz.f32 %0, %1;" : "=f"(r) : "f"(x)); return r;
}
__device__ __forceinline__ float rcpf(float x) {
    float r; asm("rcp.approx.ftz.f32 %0, %1;" : "=f"(r) : "f"(x)); return r;
}

#define L2E 1.4426950408889634f

__device__ __forceinline__ float fsig(float x) {
    return rcpf(1.0f + ex2f(-L2E * x));
}
__device__ __forceinline__ float ftanh(float x) {
    return 2.0f * rcpf(1.0f + ex2f(-2.0f * L2E * x)) - 1.0f;
}

// One persistent block per (batch, direction). 384 threads; thread j owns
// column j of the 3H pre-activations with Wh[:,j] packed f32x2 in registers.
// warps 0-3  (j<128):   r-gate   -> r_s
// warps 4-7  (j<256):   z-gate   -> omz2_s = 2(1-z), zhm_s = z*h-(1-z)
// warps 8-11 (j>=256):  n-gate   -> h update
__global__ void __launch_bounds__(H3, 1) gru_persist_kernel(
    const float* __restrict__ y, const float* __restrict__ u,
    const float* __restrict__ Wi_f, const float* __restrict__ bi_f,
    const float* __restrict__ Wh_f, const float* __restrict__ bhn_f,
    const float* __restrict__ Wi_b, const float* __restrict__ bi_b,
    const float* __restrict__ Wh_b, const float* __restrict__ bhn_b)
{
    const int blk = blockIdx.x;        // 0..127
    const int b   = blk & (BATCH - 1); // batch index
    const int dir = blk >> 6;          // 0 = fwd, 1 = bwd
    const int j   = threadIdx.x;       // 0..383

    const float* Wi  = dir ? Wi_b  : Wi_f;
    const float* bi  = dir ? bi_b  : bi_f;
    const float* Wh  = dir ? Wh_b  : Wh_f;
    const float* bhn = dir ? bhn_b : bhn_f;

    // ---- shared state ----
    __shared__ __align__(16) float h_s[H];        // hidden state
    __shared__ float r_s[H], omz2_s[H], zhm_s[H];
    __shared__ __align__(16) float4 yu_s[TILE * 2];   // per step: y(4)+u(4)
    __shared__ __align__(16) float4 wi4_s[2 * H3];    // Wi columns, 2 float4 each
    __shared__ float bi_s[H3];

    // ---- register-resident recurrent weights, packed pairs along k ----
    ull_t w2[H / 2];
#pragma unroll
    for (int kk = 0; kk < H / 2; ++kk)
        w2[kk] = pack2(Wh[(2 * kk) * H3 + j], Wh[(2 * kk + 1) * H3 + j]);

    // stage input-projection weights into smem (per-column packed float4)
    wi4_s[j]      = make_float4(Wi[0 * H3 + j], Wi[1 * H3 + j],
                                Wi[2 * H3 + j], Wi[3 * H3 + j]);
    wi4_s[H3 + j] = make_float4(Wi[4 * H3 + j], Wi[5 * H3 + j],
                                Wi[6 * H3 + j], Wi[7 * H3 + j]);
    bi_s[j] = bi[j];
    const float bhn_i = (j >= 2 * H) ? bhn[j - 2 * H] : 0.0f;

    if (j < H) h_s[j] = 0.0f;
    __syncthreads();

    float hsum = 0.0f;                       // running sum (n-threads only)

    const int nchunk = TT / TILE;
    for (int c = 0; c < nchunk; ++c) {
        const int t0 = dir ? (TT - (c + 1) * TILE) : (c * TILE);

        if (j < TILE) {                      // stage chunk inputs
            const int t = t0 + j;
            yu_s[2 * j]     = *(const float4*)(y + ((size_t)b * TT + t) * 4);
            yu_s[2 * j + 1] = *(const float4*)(u + ((size_t)b * TT + t) * 4);
        }
        __syncthreads();

        const int tt0 = dir ? (TILE - 1) : 0;
        const int sgn = dir ? -1 : 1;

        for (int s = 0; s < TILE; ++s) {
            const int tt = tt0 + sgn * s;

            // ---- phase 1: pre-activations (all threads) ----
            const float4 ya = yu_s[2 * tt];       // broadcast
            const float4 ub = yu_s[2 * tt + 1];
            const float4 wa = wi4_s[j];           // lane-consecutive
            const float4 wb = wi4_s[H3 + j];
            float xw = bi_s[j];
            xw = fmaf(ya.x, wa.x, xw); xw = fmaf(ya.y, wa.y, xw);
            xw = fmaf(ya.z, wa.z, xw); xw = fmaf(ya.w, wa.w, xw);
            xw = fmaf(ub.x, wb.x, xw); xw = fmaf(ub.y, wb.y, xw);
            xw = fmaf(ub.z, wb.z, xw); xw = fmaf(ub.w, wb.w, xw);

            // packed dot: h[0:128] . w2
            const ulonglong2* h2 = (const ulonglong2*)h_s;
            ull_t a0 = 0ull, a1 = 0ull;
#pragma unroll
            for (int m = 0; m < H / 4; ++m) {
                const ulonglong2 hv = h2[m];      // broadcast
                a0 = ffma2(hv.x, w2[2 * m],     a0);
                a1 = ffma2(hv.y, w2[2 * m + 1], a1);
            }
            const ull_t asum = fadd2(a0, a1);
            const float dot = lo2(asum) + hi2(asum);

            float nb = 0.0f;
            if (j < H) {
                r_s[j] = fsig(xw + dot);
                asm volatile("bar.arrive 1, 384;");
            } else if (j < 2 * H) {
                const int i = j - H;
                const float z = fsig(xw + dot);
                const float hold = h_s[i];
                omz2_s[i] = 2.0f - 2.0f * z;
                zhm_s[i]  = fmaf(z, hold + 1.0f, -1.0f);   // z*h - (1-z)
                asm volatile("bar.arrive 1, 384;");
            } else {
                nb = dot + bhn_i;
                asm volatile("bar.sync 1, 384;");          // wait for r/z
                // ---- phase 2: n-gate threads update h ----
                const int i = j - 2 * H;
                const float om = omz2_s[i];
                const float zm = zhm_s[i];
                const float r  = r_s[i];
                const float arg = fmaf(r, nb, xw);
                const float q   = ex2f(-2.0f * L2E * arg);
                const float rc  = rcpf(1.0f + q);
                const float hn  = fmaf(rc, om, zm);        // (1-z)*tanh + z*h
                hsum += hn;
                h_s[i] = hn;
            }
            __syncthreads();
        }
    }

    if (j >= 2 * H)
        g_feat[b * (2 * H) + dir * H + (j - 2 * H)] = hsum * (1.0f / (float)TT);
}

// MLP heads: 256 -> 128 -> 64 -> 20, tanh, tanh, linear.
// One block per (batch, head); weights streamed from gmem (L2-shared).
__global__ void __launch_bounds__(128) mlp_kernel(
    const float* __restrict__ mW0, const float* __restrict__ mb0,
    const float* __restrict__ mW1, const float* __restrict__ mb1,
    const float* __restrict__ mW2, const float* __restrict__ mb2,
    const float* __restrict__ sW0, const float* __restrict__ sb0,
    const float* __restrict__ sW1, const float* __restrict__ sb1,
    const float* __restrict__ sW2, const float* __restrict__ sb2,
    float* __restrict__ out)
{
    const int b    = blockIdx.x & (BATCH - 1);
    const int head = blockIdx.x >> 6;
    const int j    = threadIdx.x;

    const float* W0 = head ? sW0 : mW0;
    const float* b0 = head ? sb0 : mb0;
    const float* W1 = head ? sW1 : mW1;
    const float* b1 = head ? sb1 : mb1;
    const float* W2 = head ? sW2 : mW2;
    const float* b2 = head ? sb2 : mb2;

    __shared__ float feat_s[256];
    __shared__ float h1_s[128];
    __shared__ float h2_s[64];

    feat_s[j]       = g_feat[b * 256 + j];
    feat_s[j + 128] = g_feat[b * 256 + j + 128];
    __syncthreads();

    // layer 0: 256 -> 128
    {
        float acc = b0[j];
#pragma unroll 8
        for (int i = 0; i < 256; ++i)
            acc = fmaf(feat_s[i], __ldg(W0 + (size_t)i * 128 + j), acc);
        h1_s[j] = ftanh(acc);
    }
    __syncthreads();

    // layer 1: 128 -> 64
    if (j < 64) {
        float acc = b1[j];
#pragma unroll 8
        for (int i = 0; i < 128; ++i)
            acc = fmaf(h1_s[i], __ldg(W1 + (size_t)i * 64 + j), acc);
        h2_s[j] = ftanh(acc);
    }
    __syncthreads();

    // layer 2: 64 -> 20
    if (j < 20) {
        float acc = b2[j];
#pragma unroll
        for (int i = 0; i < 64; ++i)
            acc = fmaf(h2_s[i], __ldg(W2 + (size_t)i * 20 + j), acc);
        out[head * (BATCH * 20) + b * 20 + j] = acc;
    }
}

extern "C" void kernel_launch(void* const* d_in, const int* in_sizes, int n_in,
                              void* d_out, int out_size)
{
    const float* y     = (const float*)d_in[0];
    const float* u     = (const float*)d_in[1];
    const float* Wi_f  = (const float*)d_in[2];
    const float* bi_f  = (const float*)d_in[3];
    const float* Wh_f  = (const float*)d_in[4];
    const float* bhn_f = (const float*)d_in[5];
    const float* Wi_b  = (const float*)d_in[6];
    const float* bi_b  = (const float*)d_in[7];
    const float* Wh_b  = (const float*)d_in[8];
    const float* bhn_b = (const float*)d_in[9];
    const float* mW0   = (const float*)d_in[10];
    const float* mb0   = (const float*)d_in[11];
    const float* mW1   = (const float*)d_in[12];
    const float* mb1   = (const float*)d_in[13];
    const float* mW2   = (const float*)d_in[14];
    const float* mb2   = (const float*)d_in[15];
    const float* sW0   = (const float*)d_in[16];
    const float* sb0   = (const float*)d_in[17];
    const float* sW1   = (const float*)d_in[18];
    const float* sb1   = (const float*)d_in[19];
    const float* sW2   = (const float*)d_in[20];
    const float* sb2   = (const float*)d_in[21];

    gru_persist_kernel<<<BATCH * 2, H3>>>(y, u, Wi_f, bi_f, Wh_f, bhn_f,
                                          Wi_b, bi_b, Wh_b, bhn_b);
    mlp_kernel<<<BATCH * 2, 128>>>(mW0, mb0, mW1, mb1, mW2, mb2,
                                   sW0, sb0, sW1, sb1, sW2, sb2,
                                   (float*)d_out);
}

// round 5
// speedup vs baseline: 1.1446x; 1.1106x over previous
#include <cuda_runtime.h>
#include <math.h>

#define H      128
#define H3     384
#define BATCH  64
#define TT     2048
#define TILE   128   // time steps staged per smem chunk

typedef unsigned long long ull_t;

// feat[b*256 + dir*128 + i] = mean over t of hidden state
__device__ float g_feat[BATCH * 2 * H];

__device__ __forceinline__ ull_t pack2(float lo, float hi) {
    return (ull_t)__float_as_uint(lo) | ((ull_t)__float_as_uint(hi) << 32);
}
__device__ __forceinline__ float lo2(ull_t v) { return __uint_as_float((unsigned)v); }
__device__ __forceinline__ float hi2(ull_t v) { return __uint_as_float((unsigned)(v >> 32)); }

__device__ __forceinline__ ull_t ffma2(ull_t a, ull_t b, ull_t c) {
    ull_t d;
    asm("fma.rn.f32x2 %0, %1, %2, %3;" : "=l"(d) : "l"(a), "l"(b), "l"(c));
    return d;
}
__device__ __forceinline__ ull_t fadd2(ull_t a, ull_t b) {
    ull_t d;
    asm("add.rn.f32x2 %0, %1, %2;" : "=l"(d) : "l"(a), "l"(b));
    return d;
}
__device__ __forceinline__ float ex2f(float x) {
    float r; asm("ex2.approx.ftz.f32 %0, %1;" : "=f"(r) : "f"(x)); return r;
}
__device__ __forceinline__ float rcpf(float x) {
    float r; asm("rcp.approx.ftz.f32 %0, %1;" : "=f"(r) : "f"(x)); return r;
}

#define L2E 1.4426950408889634f

__device__ __forceinline__ float fsig(float x) {
    return rcpf(1.0f + ex2f(-L2E * x));
}
__device__ __forceinline__ float ftanh(float x) {
    return 2.0f * rcpf(1.0f + ex2f(-2.0f * L2E * x)) - 1.0f;
}

// One persistent block per (batch, direction). 384 threads; thread j owns
// column j of the 3H pre-activations with Wh[:,j] packed f32x2 in registers
// and Wi[:,j] scalar in registers.
// warps 0-3  (j<128):   r-gate   -> r_s
// warps 4-7  (j<256):   z-gate   -> omz2_s = 2(1-z), zhm_s = z*h-(1-z)
// warps 8-11 (j>=256):  n-gate   -> h update
__global__ void __launch_bounds__(H3, 1) gru_persist_kernel(
    const float* __restrict__ y, const float* __restrict__ u,
    const float* __restrict__ Wi_f, const float* __restrict__ bi_f,
    const float* __restrict__ Wh_f, const float* __restrict__ bhn_f,
    const float* __restrict__ Wi_b, const float* __restrict__ bi_b,
    const float* __restrict__ Wh_b, const float* __restrict__ bhn_b)
{
    const int blk = blockIdx.x;        // 0..127
    const int b   = blk & (BATCH - 1); // batch index
    const int dir = blk >> 6;          // 0 = fwd, 1 = bwd
    const int j   = threadIdx.x;       // 0..383

    const float* Wi  = dir ? Wi_b  : Wi_f;
    const float* bi  = dir ? bi_b  : bi_f;
    const float* Wh  = dir ? Wh_b  : Wh_f;
    const float* bhn = dir ? bhn_b : bhn_f;

    // ---- register-resident weights ----
    ull_t w2[H / 2];                   // Wh[:,j], packed pairs along k
#pragma unroll
    for (int kk = 0; kk < H / 2; ++kk)
        w2[kk] = pack2(Wh[(2 * kk) * H3 + j], Wh[(2 * kk + 1) * H3 + j]);

    float wi[8];                       // Wi[:,j], scalar (R2-proven layout)
#pragma unroll
    for (int d = 0; d < 8; ++d) wi[d] = Wi[d * H3 + j];

    const float bij   = bi[j];
    const float bhn_i = (j >= 2 * H) ? bhn[j - 2 * H] : 0.0f;

    // ---- shared state ----
    __shared__ __align__(16) float h_s[H];            // hidden state
    __shared__ float r_s[H], omz2_s[H], zhm_s[H];
    __shared__ __align__(16) float4 yu_s[TILE * 2];   // per step: y(4)+u(4)

    if (j < H) h_s[j] = 0.0f;
    __syncthreads();

    float hsum = 0.0f;                 // running sum (n-threads only)

    const int nchunk = TT / TILE;
    for (int c = 0; c < nchunk; ++c) {
        const int t0 = dir ? (TT - (c + 1) * TILE) : (c * TILE);

        if (j < TILE) {                // stage chunk inputs (r-warps)
            const int t = t0 + j;
            yu_s[2 * j]     = *(const float4*)(y + ((size_t)b * TT + t) * 4);
            yu_s[2 * j + 1] = *(const float4*)(u + ((size_t)b * TT + t) * 4);
        }
        __syncthreads();

        const int tt0 = dir ? (TILE - 1) : 0;
        const int sgn = dir ? -1 : 1;

        // prologue: xw for step 0 of this chunk
        float xw;
        {
            const float4 ya = yu_s[2 * tt0];
            const float4 ub = yu_s[2 * tt0 + 1];
            float a = bij;
            a = fmaf(ya.x, wi[0], a); a = fmaf(ya.y, wi[1], a);
            a = fmaf(ya.z, wi[2], a); a = fmaf(ya.w, wi[3], a);
            a = fmaf(ub.x, wi[4], a); a = fmaf(ub.y, wi[5], a);
            a = fmaf(ub.z, wi[6], a); a = fmaf(ub.w, wi[7], a);
            xw = a;
        }

        for (int s = 0; s < TILE; ++s) {
            // ---- phase 1: recurrent dot (all threads); xw already ready ----
            const ulonglong2* h2 = (const ulonglong2*)h_s;
            ull_t a0 = 0ull, a1 = 0ull;
#pragma unroll
            for (int m = 0; m < H / 4; ++m) {
                const ulonglong2 hv = h2[m];          // broadcast
                a0 = ffma2(hv.x, w2[2 * m],     a0);
                a1 = ffma2(hv.y, w2[2 * m + 1], a1);
            }
            const ull_t asum = fadd2(a0, a1);
            const float dot = lo2(asum) + hi2(asum);

            // xw for next step (input-only, off the critical path)
            float xw_next = 0.0f;
            const int tt_n = tt0 + sgn * (s + 1);
            const bool has_next = (s + 1 < TILE);

            if (j < H) {
                r_s[j] = fsig(xw + dot);
                if (has_next) {
                    const float4 ya = yu_s[2 * tt_n];
                    const float4 ub = yu_s[2 * tt_n + 1];
                    float a = bij;
                    a = fmaf(ya.x, wi[0], a); a = fmaf(ya.y, wi[1], a);
                    a = fmaf(ya.z, wi[2], a); a = fmaf(ya.w, wi[3], a);
                    a = fmaf(ub.x, wi[4], a); a = fmaf(ub.y, wi[5], a);
                    a = fmaf(ub.z, wi[6], a); a = fmaf(ub.w, wi[7], a);
                    xw_next = a;
                }
                asm volatile("bar.arrive 1, 384;");
            } else if (j < 2 * H) {
                const int i = j - H;
                const float z = fsig(xw + dot);
                const float hold = h_s[i];
                omz2_s[i] = 2.0f - 2.0f * z;
                zhm_s[i]  = fmaf(z, hold + 1.0f, -1.0f);  // z*h - (1-z)
                if (has_next) {
                    const float4 ya = yu_s[2 * tt_n];
                    const float4 ub = yu_s[2 * tt_n + 1];
                    float a = bij;
                    a = fmaf(ya.x, wi[0], a); a = fmaf(ya.y, wi[1], a);
                    a = fmaf(ya.z, wi[2], a); a = fmaf(ya.w, wi[3], a);
                    a = fmaf(ub.x, wi[4], a); a = fmaf(ub.y, wi[5], a);
                    a = fmaf(ub.z, wi[6], a); a = fmaf(ub.w, wi[7], a);
                    xw_next = a;
                }
                asm volatile("bar.arrive 1, 384;");
            } else {
                const float nb = dot + bhn_i;
                if (has_next) {                       // fills the bar1 wait
                    const float4 ya = yu_s[2 * tt_n];
                    const float4 ub = yu_s[2 * tt_n + 1];
                    float a = bij;
                    a = fmaf(ya.x, wi[0], a); a = fmaf(ya.y, wi[1], a);
                    a = fmaf(ya.z, wi[2], a); a = fmaf(ya.w, wi[3], a);
                    a = fmaf(ub.x, wi[4], a); a = fmaf(ub.y, wi[5], a);
                    a = fmaf(ub.z, wi[6], a); a = fmaf(ub.w, wi[7], a);
                    xw_next = a;
                }
                asm volatile("bar.sync 1, 384;");     // wait for r/z
                // ---- phase 2: n-gate threads update h ----
                const int i = j - 2 * H;
                const float om = omz2_s[i];
                const float zm = zhm_s[i];
                const float r  = r_s[i];
                const float arg = fmaf(r, nb, xw);
                const float q   = ex2f(-2.0f * L2E * arg);
                const float rc  = rcpf(1.0f + q);
                const float hn  = fmaf(rc, om, zm);   // (1-z)*tanh + z*h
                hsum += hn;
                h_s[i] = hn;
            }
            __syncthreads();                          // h ready for next step
            xw = xw_next;
        }
    }

    if (j >= 2 * H)
        g_feat[b * (2 * H) + dir * H + (j - 2 * H)] = hsum * (1.0f / (float)TT);
}

// MLP heads: 256 -> 128 -> 64 -> 20, tanh, tanh, linear.
// One block per (batch, head); weights streamed from gmem (L2-shared).
__global__ void __launch_bounds__(128) mlp_kernel(
    const float* __restrict__ mW0, const float* __restrict__ mb0,
    const float* __restrict__ mW1, const float* __restrict__ mb1,
    const float* __restrict__ mW2, const float* __restrict__ mb2,
    const float* __restrict__ sW0, const float* __restrict__ sb0,
    const float* __restrict__ sW1, const float* __restrict__ sb1,
    const float* __restrict__ sW2, const float* __restrict__ sb2,
    float* __restrict__ out)
{
    const int b    = blockIdx.x & (BATCH - 1);
    const int head = blockIdx.x >> 6;
    const int j    = threadIdx.x;

    const float* W0 = head ? sW0 : mW0;
    const float* b0 = head ? sb0 : mb0;
    const float* W1 = head ? sW1 : mW1;
    const float* b1 = head ? sb1 : mb1;
    const float* W2 = head ? sW2 : mW2;
    const float* b2 = head ? sb2 : mb2;

    __shared__ float feat_s[256];
    __shared__ float h1_s[128];
    __shared__ float h2_s[64];

    feat_s[j]       = g_feat[b * 256 + j];
    feat_s[j + 128] = g_feat[b * 256 + j + 128];
    __syncthreads();

    // layer 0: 256 -> 128
    {
        float acc = b0[j];
#pragma unroll 8
        for (int i = 0; i < 256; ++i)
            acc = fmaf(feat_s[i], __ldg(W0 + (size_t)i * 128 + j), acc);
        h1_s[j] = ftanh(acc);
    }
    __syncthreads();

    // layer 1: 128 -> 64
    if (j < 64) {
        float acc = b1[j];
#pragma unroll 8
        for (int i = 0; i < 128; ++i)
            acc = fmaf(h1_s[i], __ldg(W1 + (size_t)i * 64 + j), acc);
        h2_s[j] = ftanh(acc);
    }
    __syncthreads();

    // layer 2: 64 -> 20
    if (j < 20) {
        float acc = b2[j];
#pragma unroll
        for (int i = 0; i < 64; ++i)
            acc = fmaf(h2_s[i], __ldg(W2 + (size_t)i * 20 + j), acc);
        out[head * (BATCH * 20) + b * 20 + j] = acc;
    }
}

extern "C" void kernel_launch(void* const* d_in, const int* in_sizes, int n_in,
                              void* d_out, int out_size)
{
    const float* y     = (const float*)d_in[0];
    const float* u     = (const float*)d_in[1];
    const float* Wi_f  = (const float*)d_in[2];
    const float* bi_f  = (const float*)d_in[3];
    const float* Wh_f  = (const float*)d_in[4];
    const float* bhn_f = (const float*)d_in[5];
    const float* Wi_b  = (const float*)d_in[6];
    const float* bi_b  = (const float*)d_in[7];
    const float* Wh_b  = (const float*)d_in[8];
    const float* bhn_b = (const float*)d_in[9];
    const float* mW0   = (const float*)d_in[10];
    const float* mb0   = (const float*)d_in[11];
    const float* mW1   = (const float*)d_in[12];
    const float* mb1   = (const float*)d_in[13];
    const float* mW2   = (const float*)d_in[14];
    const float* mb2   = (const float*)d_in[15];
    const float* sW0   = (const float*)d_in[16];
    const float* sb0   = (const float*)d_in[17];
    const float* sW1   = (const float*)d_in[18];
    const float* sb1   = (const float*)d_in[19];
    const float* sW2   = (const float*)d_in[20];
    const float* sb2   = (const float*)d_in[21];

    gru_persist_kernel<<<BATCH * 2, H3>>>(y, u, Wi_f, bi_f, Wh_f, bhn_f,
                                          Wi_b, bi_b, Wh_b, bhn_b);
    mlp_kernel<<<BATCH * 2, 128>>>(mW0, mb0, mW1, mb1, mW2, mb2,
                                   sW0, sb0, sW1, sb1, sW2, sb2,
                                   (float*)d_out);
}